// round 5
// baseline (speedup 1.0000x reference)
#include <cuda_runtime.h>
#include <math.h>

#define BB 8
#define LL 1024
#define DD 512
#define HH 8
#define DKK 64

// Scratch (__device__ globals; no runtime allocation)
__device__ float g_Q[BB*HH*LL*DKK];   // (B,H,L,DK) fp32
__device__ float g_K[BB*HH*LL*DKK];
__device__ float g_V[BB*HH*LL*DKK];
__device__ float g_X[BB*LL*DD];       // attention output (B,L,D) fp32

// m16n8k8 tf32 MMA. A row-major (16x8), B col-major (8x8), C fp32.
__device__ __forceinline__ void mma8(float* c, const unsigned* a, unsigned b0, unsigned b1) {
    asm volatile(
        "mma.sync.aligned.m16n8k8.row.col.f32.tf32.tf32.f32 "
        "{%0,%1,%2,%3}, {%4,%5,%6,%7}, {%8,%9}, {%0,%1,%2,%3};\n"
        : "+f"(c[0]), "+f"(c[1]), "+f"(c[2]), "+f"(c[3])
        : "r"(a[0]), "r"(a[1]), "r"(a[2]), "r"(a[3]), "r"(b0), "r"(b1));
}

__device__ __forceinline__ unsigned f2tf(float x) {
    unsigned r;
    asm("cvt.rna.tf32.f32 %0, %1;" : "=r"(r) : "f"(x));
    return r;
}
__device__ __forceinline__ float2 split2(float x) {
    unsigned hi = f2tf(x);
    unsigned lo = f2tf(x - __uint_as_float(hi));
    return make_float2(__uint_as_float(hi), __uint_as_float(lo));
}

// ---------------------------------------------------------------------------
// 3xTF32 GEMM, hi/lo pre-split in smem (float2 interleaved).
// C[m,n] = sum_k A[m,k]*W[n,k] + bias[n]. Block 128x64, BK=32, 256 thr.
// gridDim.z selects one of up to 3 (A,W,bias,C) tuples (fused projections).
// NOTE: GST2 is odd -> float4 stores into As2/Bs2 would be misaligned on odd
// rows (row*35*8 B is not 16B-aligned). All smem fills use float2 stores.
// ---------------------------------------------------------------------------
#define GST2 35
#define SMEM_GEMM ((128 + 64) * GST2 * (int)sizeof(float2))   // 53,760 B

__global__ __launch_bounds__(256) void gemm3(
    const float* __restrict__ A0, const float* __restrict__ W0,
    const float* __restrict__ bias0, float* __restrict__ C0,
    const float* __restrict__ A1, const float* __restrict__ W1,
    const float* __restrict__ bias1, float* __restrict__ C1,
    const float* __restrict__ A2, const float* __restrict__ W2,
    const float* __restrict__ bias2, float* __restrict__ C2,
    int headmode)
{
    extern __shared__ float2 smg[];
    float2* As2 = smg;                 // [128][GST2]
    float2* Bs2 = smg + 128 * GST2;    // [64][GST2]

    const float* A = A0; const float* W = W0; const float* bias = bias0; float* C = C0;
    if (blockIdx.z == 1) { A = A1; W = W1; bias = bias1; C = C1; }
    else if (blockIdx.z == 2) { A = A2; W = W2; bias = bias2; C = C2; }

    const int tid  = threadIdx.x;
    const int lane = tid & 31;
    const int warp = tid >> 5;
    const int g = lane >> 2, t = lane & 3;
    const int wm = warp & 3, wn = warp >> 2;     // 4 (m) x 2 (n)
    const int m0 = blockIdx.y << 7, n0 = blockIdx.x << 6;

    float c[2][4][4];
    #pragma unroll
    for (int mt = 0; mt < 2; mt++)
        #pragma unroll
        for (int nt = 0; nt < 4; nt++)
            #pragma unroll
            for (int k = 0; k < 4; k++) c[mt][nt][k] = 0.f;

    const float* Abase = A + (size_t)m0 * DD;
    const float* Wbase = W + (size_t)n0 * DD;

    float4 ra[4], rb[2];
    #pragma unroll
    for (int i = 0; i < 4; i++) {
        int idx = tid + (i << 8);
        ra[i] = *(const float4*)(Abase + (size_t)(idx >> 3) * DD + ((idx & 7) << 2));
    }
    #pragma unroll
    for (int i = 0; i < 2; i++) {
        int idx = tid + (i << 8);
        rb[i] = *(const float4*)(Wbase + (size_t)(idx >> 3) * DD + ((idx & 7) << 2));
    }

    for (int k0 = 0; k0 < DD; k0 += 32) {
        __syncthreads();
        #pragma unroll
        for (int i = 0; i < 4; i++) {
            int idx = tid + (i << 8);
            float2* dst = As2 + (idx >> 3) * GST2 + ((idx & 7) << 2);
            dst[0] = split2(ra[i].x);
            dst[1] = split2(ra[i].y);
            dst[2] = split2(ra[i].z);
            dst[3] = split2(ra[i].w);
        }
        #pragma unroll
        for (int i = 0; i < 2; i++) {
            int idx = tid + (i << 8);
            float2* dst = Bs2 + (idx >> 3) * GST2 + ((idx & 7) << 2);
            dst[0] = split2(rb[i].x);
            dst[1] = split2(rb[i].y);
            dst[2] = split2(rb[i].z);
            dst[3] = split2(rb[i].w);
        }
        __syncthreads();

        if (k0 + 32 < DD) {
            #pragma unroll
            for (int i = 0; i < 4; i++) {
                int idx = tid + (i << 8);
                ra[i] = *(const float4*)(Abase + (size_t)(idx >> 3) * DD + k0 + 32 + ((idx & 7) << 2));
            }
            #pragma unroll
            for (int i = 0; i < 2; i++) {
                int idx = tid + (i << 8);
                rb[i] = *(const float4*)(Wbase + (size_t)(idx >> 3) * DD + k0 + 32 + ((idx & 7) << 2));
            }
        }

        #pragma unroll
        for (int kt = 0; kt < 4; kt++) {
            float2 af[2][4];
            #pragma unroll
            for (int mt = 0; mt < 2; mt++) {
                int r = wm * 32 + mt * 16 + g;
                af[mt][0] = As2[ r      * GST2 + kt*8 + t    ];
                af[mt][1] = As2[(r + 8) * GST2 + kt*8 + t    ];
                af[mt][2] = As2[ r      * GST2 + kt*8 + t + 4];
                af[mt][3] = As2[(r + 8) * GST2 + kt*8 + t + 4];
            }
            float2 bf[4][2];
            #pragma unroll
            for (int nt = 0; nt < 4; nt++) {
                int r = wn * 32 + nt * 8 + g;
                bf[nt][0] = Bs2[r * GST2 + kt*8 + t    ];
                bf[nt][1] = Bs2[r * GST2 + kt*8 + t + 4];
            }
            #pragma unroll
            for (int mt = 0; mt < 2; mt++) {
                unsigned ah[4], al[4];
                #pragma unroll
                for (int k = 0; k < 4; k++) {
                    ah[k] = __float_as_uint(af[mt][k].x);
                    al[k] = __float_as_uint(af[mt][k].y);
                }
                #pragma unroll
                for (int nt = 0; nt < 4; nt++) {
                    unsigned bh0 = __float_as_uint(bf[nt][0].x);
                    unsigned bh1 = __float_as_uint(bf[nt][1].x);
                    mma8(c[mt][nt], al, bh0, bh1);
                    mma8(c[mt][nt], ah, __float_as_uint(bf[nt][0].y),
                                        __float_as_uint(bf[nt][1].y));
                    mma8(c[mt][nt], ah, bh0, bh1);
                }
            }
        }
    }

    // epilogue: bias + store
    #pragma unroll
    for (int nt = 0; nt < 4; nt++) {
        int n = n0 + wn * 32 + nt * 8 + 2 * t;
        float b0 = bias[n], b1 = bias[n + 1];
        #pragma unroll
        for (int mt = 0; mt < 2; mt++) {
            int m = m0 + wm * 32 + mt * 16 + g;
            if (headmode) {
                int b_ = m >> 10, l = m & 1023;
                int h = n >> 6, dk = n & 63;
                float* p0 = C + (((size_t)b_ * HH + h) * LL + l) * DKK + dk;
                float* p1 = C + (((size_t)b_ * HH + h) * LL + (l + 8)) * DKK + dk;
                *(float2*)p0 = make_float2(c[mt][nt][0] + b0, c[mt][nt][1] + b1);
                *(float2*)p1 = make_float2(c[mt][nt][2] + b0, c[mt][nt][3] + b1);
            } else {
                float* p0 = C + (size_t)m * DD + n;
                float* p1 = C + (size_t)(m + 8) * DD + n;
                *(float2*)p0 = make_float2(c[mt][nt][0] + b0, c[mt][nt][1] + b1);
                *(float2*)p1 = make_float2(c[mt][nt][2] + b0, c[mt][nt][3] + b1);
            }
        }
    }
}

// ---------------------------------------------------------------------------
// Flash attention, tf32 MMA, hi/lo pre-split K/V in smem (float2).
// Block = (bh, 128 q-rows), 256 threads (8 warps x 16 q-rows).
// QK^T 3xTF32, P@V 2xTF32 (P tf32-rounded). KV tile = 64.
// smem: K2,V2 [64][66] float2 + Ps [128][68] float = 102,400 B.
// (AK=66: row stride 528 B, 16B-aligned -> float4 smem fills OK.
//  APS=68 floats: row stride 272 B, 16B-aligned.)
// ---------------------------------------------------------------------------
#define AK 66
#define APS 68
#define SMEM_ATTN (2 * 64 * AK * (int)sizeof(float2) + 128 * APS * (int)sizeof(float))

__global__ __launch_bounds__(256) void attn_tf32(
    const float* __restrict__ dist, const unsigned char* __restrict__ mask,
    const float* __restrict__ logwb)
{
    extern __shared__ char smc[];
    float2* K2 = (float2*)smc;            // [64][AK]
    float2* V2 = K2 + 64 * AK;            // [64][AK]
    float*  Ps = (float*)(V2 + 64 * AK);  // [128][APS]

    const int tid  = threadIdx.x;
    const int lane = tid & 31;
    const int warp = tid >> 5;            // 0..7
    const int g = lane >> 2, t = lane & 3;

    const int bh = blockIdx.y;
    const int b  = bh >> 3, h = bh & 7;
    const int q0 = blockIdx.x << 7;

    const float wb = __expf(logwb[h]);

    // Stage Q (scaled by 0.125) into Ps, then split into hi/lo A-frags.
    const float* Qg = g_Q + ((size_t)bh * LL + q0) * DKK;
    for (int i = tid; i < 2048; i += 256) {       // 128 rows x 16 float4
        int r = i >> 4, c4 = (i & 15) << 2;
        float4 v = *(const float4*)(Qg + (size_t)r * DKK + c4);
        v.x *= 0.125f; v.y *= 0.125f; v.z *= 0.125f; v.w *= 0.125f;
        *(float4*)&Ps[r * APS + c4] = v;
    }
    __syncthreads();

    unsigned qh[8][4], ql[8][4];
    {
        int r = warp * 16 + g;
        #pragma unroll
        for (int kt = 0; kt < 8; kt++) {
            float2 s;
            s = split2(Ps[ r      * APS + kt*8 + t    ]); qh[kt][0] = __float_as_uint(s.x); ql[kt][0] = __float_as_uint(s.y);
            s = split2(Ps[(r + 8) * APS + kt*8 + t    ]); qh[kt][1] = __float_as_uint(s.x); ql[kt][1] = __float_as_uint(s.y);
            s = split2(Ps[ r      * APS + kt*8 + t + 4]); qh[kt][2] = __float_as_uint(s.x); ql[kt][2] = __float_as_uint(s.y);
            s = split2(Ps[(r + 8) * APS + kt*8 + t + 4]); qh[kt][3] = __float_as_uint(s.x); ql[kt][3] = __float_as_uint(s.y);
        }
    }

    float o[8][4];
    #pragma unroll
    for (int nt = 0; nt < 8; nt++)
        #pragma unroll
        for (int k = 0; k < 4; k++) o[nt][k] = 0.f;
    float mrow[2] = {-1e30f, -1e30f};
    float lrow[2] = {0.f, 0.f};

    const float* Kg = g_K + (size_t)bh * LL * DKK;
    const float* Vg = g_V + (size_t)bh * LL * DKK;
    const float* db = dist + (size_t)b * LL * LL;
    const unsigned char* mb = mask + (size_t)b * LL * LL;

    const int qr0 = q0 + warp * 16 + g;
    const int pr0 = warp * 16 + g;

    for (int k0 = 0; k0 < LL; k0 += 64) {
        __syncthreads();   // all warps done with previous K2/V2
        for (int i = tid; i < 1024; i += 256) {   // 64 rows x 16 float4
            int r = i >> 4, c4 = (i & 15) << 2;
            float4 kv = *(const float4*)(Kg + (size_t)(k0 + r) * DKK + c4);
            float4 vv = *(const float4*)(Vg + (size_t)(k0 + r) * DKK + c4);
            float2 k0s = split2(kv.x), k1s = split2(kv.y), k2s = split2(kv.z), k3s = split2(kv.w);
            float2 v0s = split2(vv.x), v1s = split2(vv.y), v2s = split2(vv.z), v3s = split2(vv.w);
            float2* kd = K2 + r * AK + c4;
            float2* vd = V2 + r * AK + c4;
            *(float4*)(kd)     = make_float4(k0s.x, k0s.y, k1s.x, k1s.y);
            *(float4*)(kd + 2) = make_float4(k2s.x, k2s.y, k3s.x, k3s.y);
            *(float4*)(vd)     = make_float4(v0s.x, v0s.y, v1s.x, v1s.y);
            *(float4*)(vd + 2) = make_float4(v2s.x, v2s.y, v3s.x, v3s.y);
        }
        __syncthreads();

        // S = Q @ K^T with 3xTF32
        float s[8][4];
        #pragma unroll
        for (int nt = 0; nt < 8; nt++)
            #pragma unroll
            for (int k = 0; k < 4; k++) s[nt][k] = 0.f;

        #pragma unroll
        for (int kt = 0; kt < 8; kt++) {
            #pragma unroll
            for (int nt = 0; nt < 8; nt++) {
                const float2* bp = K2 + (nt*8 + g) * AK + kt*8;
                float2 b0 = bp[t], b1 = bp[t + 4];
                unsigned bh0 = __float_as_uint(b0.x), bh1 = __float_as_uint(b1.x);
                mma8(s[nt], ql[kt], bh0, bh1);
                mma8(s[nt], qh[kt], __float_as_uint(b0.y), __float_as_uint(b1.y));
                mma8(s[nt], qh[kt], bh0, bh1);
            }
        }

        // distance bias + mask on C-fragments
        #pragma unroll
        for (int nt = 0; nt < 8; nt++) {
            int col = k0 + nt*8 + 2*t;
            float2 d0 = *(const float2*)(db + (size_t)qr0 * LL + col);
            float2 d1 = *(const float2*)(db + (size_t)(qr0 + 8) * LL + col);
            unsigned short mk0 = *(const unsigned short*)(mb + (size_t)qr0 * LL + col);
            unsigned short mk1 = *(const unsigned short*)(mb + (size_t)(qr0 + 8) * LL + col);
            s[nt][0] -= d0.x * wb; if (mk0 & 0xffu) s[nt][0] = -1e9f;
            s[nt][1] -= d0.y * wb; if (mk0 >> 8)    s[nt][1] = -1e9f;
            s[nt][2] -= d1.x * wb; if (mk1 & 0xffu) s[nt][2] = -1e9f;
            s[nt][3] -= d1.y * wb; if (mk1 >> 8)    s[nt][3] = -1e9f;
        }

        // online softmax
        #pragma unroll
        for (int i = 0; i < 2; i++) {
            float mx = -1e30f;
            #pragma unroll
            for (int nt = 0; nt < 8; nt++)
                mx = fmaxf(mx, fmaxf(s[nt][2*i], s[nt][2*i + 1]));
            mx = fmaxf(mx, __shfl_xor_sync(0xffffffffu, mx, 1));
            mx = fmaxf(mx, __shfl_xor_sync(0xffffffffu, mx, 2));
            float mnew  = fmaxf(mrow[i], mx);
            float alpha = __expf(mrow[i] - mnew);
            float sum = 0.f;
            #pragma unroll
            for (int nt = 0; nt < 8; nt++) {
                s[nt][2*i]     = __expf(s[nt][2*i]     - mnew);
                s[nt][2*i + 1] = __expf(s[nt][2*i + 1] - mnew);
                sum += s[nt][2*i] + s[nt][2*i + 1];
            }
            sum += __shfl_xor_sync(0xffffffffu, sum, 1);
            sum += __shfl_xor_sync(0xffffffffu, sum, 2);
            lrow[i] = lrow[i] * alpha + sum;
            mrow[i] = mnew;
            #pragma unroll
            for (int nt = 0; nt < 8; nt++) {
                o[nt][2*i]     *= alpha;
                o[nt][2*i + 1] *= alpha;
            }
        }

        // P (tf32-rounded) -> Ps (warp-private rows)
        #pragma unroll
        for (int nt = 0; nt < 8; nt++) {
            *(float2*)&Ps[ pr0      * APS + nt*8 + 2*t] =
                make_float2(__uint_as_float(f2tf(s[nt][0])), __uint_as_float(f2tf(s[nt][1])));
            *(float2*)&Ps[(pr0 + 8) * APS + nt*8 + 2*t] =
                make_float2(__uint_as_float(f2tf(s[nt][2])), __uint_as_float(f2tf(s[nt][3])));
        }
        __syncwarp();

        // O += P @ V with 2xTF32
        #pragma unroll
        for (int kt = 0; kt < 8; kt++) {
            unsigned pa[4];
            pa[0] = __float_as_uint(Ps[ pr0      * APS + kt*8 + t    ]);
            pa[1] = __float_as_uint(Ps[(pr0 + 8) * APS + kt*8 + t    ]);
            pa[2] = __float_as_uint(Ps[ pr0      * APS + kt*8 + t + 4]);
            pa[3] = __float_as_uint(Ps[(pr0 + 8) * APS + kt*8 + t + 4]);
            #pragma unroll
            for (int nt = 0; nt < 8; nt++) {
                float2 v0 = V2[(kt*8 + t    ) * AK + nt*8 + g];
                float2 v1 = V2[(kt*8 + t + 4) * AK + nt*8 + g];
                mma8(o[nt], pa, __float_as_uint(v0.y), __float_as_uint(v1.y));
                mma8(o[nt], pa, __float_as_uint(v0.x), __float_as_uint(v1.x));
            }
        }
    }

    // normalize + write X (B,L,D)
    float inv0 = 1.0f / lrow[0], inv1 = 1.0f / lrow[1];
    float* X0 = g_X + ((size_t)b * LL + qr0)     * DD + h * DKK;
    float* X1 = g_X + ((size_t)b * LL + qr0 + 8) * DD + h * DKK;
    #pragma unroll
    for (int nt = 0; nt < 8; nt++) {
        *(float2*)&X0[nt*8 + 2*t] = make_float2(o[nt][0] * inv0, o[nt][1] * inv0);
        *(float2*)&X1[nt*8 + 2*t] = make_float2(o[nt][2] * inv1, o[nt][3] * inv1);
    }
}

// ---------------------------------------------------------------------------
extern "C" void kernel_launch(void* const* d_in, const int* in_sizes, int n_in,
                              void* d_out, int out_size)
{
    const float* query = (const float*)d_in[0];
    const float* key   = (const float*)d_in[1];
    const float* value = (const float*)d_in[2];
    const float* dist  = (const float*)d_in[3];
    const unsigned char* mask = (const unsigned char*)d_in[4];
    const float* Wq = (const float*)d_in[5];
    const float* bq = (const float*)d_in[6];
    const float* Wk = (const float*)d_in[7];
    const float* bk = (const float*)d_in[8];
    const float* Wv = (const float*)d_in[9];
    const float* bv = (const float*)d_in[10];
    const float* Wo = (const float*)d_in[11];
    const float* bo = (const float*)d_in[12];
    const float* logwb = (const float*)d_in[13];

    void *pQ, *pK, *pV, *pX;
    cudaGetSymbolAddress(&pQ, g_Q);
    cudaGetSymbolAddress(&pK, g_K);
    cudaGetSymbolAddress(&pV, g_V);
    cudaGetSymbolAddress(&pX, g_X);

    cudaFuncSetAttribute(gemm3,
                         cudaFuncAttributeMaxDynamicSharedMemorySize, SMEM_GEMM);
    cudaFuncSetAttribute(attn_tf32,
                         cudaFuncAttributeMaxDynamicSharedMemorySize, SMEM_ATTN);

    // fused Q/K/V projections (z = 0,1,2)
    dim3 gp(DD / 64, (BB * LL) / 128, 3);
    gemm3<<<gp, 256, SMEM_GEMM>>>(
        query, Wq, bq, (float*)pQ,
        key,   Wk, bk, (float*)pK,
        value, Wv, bv, (float*)pV, 1);

    attn_tf32<<<dim3(LL / 128, BB * HH), 256, SMEM_ATTN>>>(dist, mask, logwb);

    // output projection
    dim3 go(DD / 64, (BB * LL) / 128, 1);
    gemm3<<<go, 256, SMEM_GEMM>>>(
        (const float*)pX, Wo, bo, (float*)d_out,
        (const float*)pX, Wo, bo, (float*)d_out,
        (const float*)pX, Wo, bo, (float*)d_out, 0);
}

// round 6
// speedup vs baseline: 2.0290x; 2.0290x over previous
#include <cuda_runtime.h>
#include <cuda_bf16.h>
#include <math.h>

#define BB 8
#define LL 1024
#define DD 512
#define HH 8
#define DKK 64

// Scratch (__device__ globals; no runtime allocation)
__device__ float g_Q[BB*HH*LL*DKK];   // (B,H,L,DK) fp32
__device__ float g_K[BB*HH*LL*DKK];
__device__ float g_V[BB*HH*LL*DKK];
__device__ float g_X[BB*LL*DD];       // attention output (B,L,D) fp32

// m16n8k16 bf16 MMA. A row-major (16x16), B col-major (16x8), C fp32.
__device__ __forceinline__ void mma16(float* c, const unsigned* a, unsigned b0, unsigned b1) {
    asm volatile(
        "mma.sync.aligned.m16n8k16.row.col.f32.bf16.bf16.f32 "
        "{%0,%1,%2,%3}, {%4,%5,%6,%7}, {%8,%9}, {%0,%1,%2,%3};\n"
        : "+f"(c[0]), "+f"(c[1]), "+f"(c[2]), "+f"(c[3])
        : "r"(a[0]), "r"(a[1]), "r"(a[2]), "r"(a[3]), "r"(b0), "r"(b1));
}

// pack two floats as bf16x2: lo 16 bits = lo_val (even k), hi 16 bits = hi_val (odd k)
__device__ __forceinline__ unsigned packbf(float lo_val, float hi_val) {
    unsigned d;
    asm("cvt.rn.bf16x2.f32 %0, %1, %2;" : "=r"(d) : "f"(hi_val), "f"(lo_val));
    return d;
}
// split a pair of floats into (hi bf16x2, lo bf16x2): x = hi + lo to ~16 mantissa bits
__device__ __forceinline__ void splitbf2(float xe, float xo, unsigned& h, unsigned& l) {
    h = packbf(xe, xo);
    float fe = __uint_as_float(h << 16);
    float fo = __uint_as_float(h & 0xffff0000u);
    l = packbf(xe - fe, xo - fo);
}

// ---------------------------------------------------------------------------
// 3xBF16 GEMM: C[m,n] = sum_k A[m,k]*W[n,k] + bias[n]
// M=8192, N=512, K=512. Block 128x64, BK=32, 256 thr (8 warps, 4m x 2n),
// warp tile 32x32 = 2 mt x 4 nt of m16n8k16; 3 MMAs per frag (hi/lo split).
// smem: Ah/Al [128][20] words + Bh/Bl [64][20] words = 30,720 B (static).
// Stride 20: bank = (20g + t) mod 32 -> all 32 lanes distinct. Conflict-free.
// ---------------------------------------------------------------------------
#define GP 20

__global__ __launch_bounds__(256) void gemm_bf16(
    const float* __restrict__ A, const float* __restrict__ W,
    const float* __restrict__ bias, float* __restrict__ C, int headmode)
{
    __shared__ unsigned Ah[128*GP], Al[128*GP], Bh[64*GP], Bl[64*GP];

    const int tid  = threadIdx.x;
    const int lane = tid & 31;
    const int warp = tid >> 5;
    const int g = lane >> 2, t = lane & 3;
    const int wm = warp & 3, wn = warp >> 2;
    const int m0 = blockIdx.y << 7, n0 = blockIdx.x << 6;

    float c[2][4][4];
    #pragma unroll
    for (int mt = 0; mt < 2; mt++)
        #pragma unroll
        for (int nt = 0; nt < 4; nt++)
            #pragma unroll
            for (int k = 0; k < 4; k++) c[mt][nt][k] = 0.f;

    const float* Abase = A + (size_t)m0 * DD;
    const float* Wbase = W + (size_t)n0 * DD;

    float4 ra[4], rb[2];
    #pragma unroll
    for (int i = 0; i < 4; i++) {
        int idx = tid + (i << 8);
        ra[i] = *(const float4*)(Abase + (size_t)(idx >> 3) * DD + ((idx & 7) << 2));
    }
    #pragma unroll
    for (int i = 0; i < 2; i++) {
        int idx = tid + (i << 8);
        rb[i] = *(const float4*)(Wbase + (size_t)(idx >> 3) * DD + ((idx & 7) << 2));
    }

    for (int k0 = 0; k0 < DD; k0 += 32) {
        __syncthreads();
        #pragma unroll
        for (int i = 0; i < 4; i++) {
            int idx = tid + (i << 8);
            int row = idx >> 3, kp = (idx & 7) << 1;    // kpair base = c4/2
            unsigned h0, l0, h1, l1;
            splitbf2(ra[i].x, ra[i].y, h0, l0);
            splitbf2(ra[i].z, ra[i].w, h1, l1);
            *(uint2*)&Ah[row*GP + kp] = make_uint2(h0, h1);
            *(uint2*)&Al[row*GP + kp] = make_uint2(l0, l1);
        }
        #pragma unroll
        for (int i = 0; i < 2; i++) {
            int idx = tid + (i << 8);
            int row = idx >> 3, kp = (idx & 7) << 1;
            unsigned h0, l0, h1, l1;
            splitbf2(rb[i].x, rb[i].y, h0, l0);
            splitbf2(rb[i].z, rb[i].w, h1, l1);
            *(uint2*)&Bh[row*GP + kp] = make_uint2(h0, h1);
            *(uint2*)&Bl[row*GP + kp] = make_uint2(l0, l1);
        }
        __syncthreads();

        if (k0 + 32 < DD) {
            #pragma unroll
            for (int i = 0; i < 4; i++) {
                int idx = tid + (i << 8);
                ra[i] = *(const float4*)(Abase + (size_t)(idx >> 3) * DD + k0 + 32 + ((idx & 7) << 2));
            }
            #pragma unroll
            for (int i = 0; i < 2; i++) {
                int idx = tid + (i << 8);
                rb[i] = *(const float4*)(Wbase + (size_t)(idx >> 3) * DD + k0 + 32 + ((idx & 7) << 2));
            }
        }

        #pragma unroll
        for (int kt = 0; kt < 2; kt++) {      // two k16 blocks per BK=32
            unsigned ah[2][4], al[2][4];
            #pragma unroll
            for (int mt = 0; mt < 2; mt++) {
                int r = wm * 32 + mt * 16 + g;
                ah[mt][0] = Ah[ r      *GP + kt*8 + t    ];
                ah[mt][1] = Ah[(r + 8) *GP + kt*8 + t    ];
                ah[mt][2] = Ah[ r      *GP + kt*8 + t + 4];
                ah[mt][3] = Ah[(r + 8) *GP + kt*8 + t + 4];
                al[mt][0] = Al[ r      *GP + kt*8 + t    ];
                al[mt][1] = Al[(r + 8) *GP + kt*8 + t    ];
                al[mt][2] = Al[ r      *GP + kt*8 + t + 4];
                al[mt][3] = Al[(r + 8) *GP + kt*8 + t + 4];
            }
            #pragma unroll
            for (int nt = 0; nt < 4; nt++) {
                int r = wn * 32 + nt * 8 + g;
                unsigned bh0 = Bh[r*GP + kt*8 + t    ];
                unsigned bh1 = Bh[r*GP + kt*8 + t + 4];
                unsigned bl0 = Bl[r*GP + kt*8 + t    ];
                unsigned bl1 = Bl[r*GP + kt*8 + t + 4];
                #pragma unroll
                for (int mt = 0; mt < 2; mt++) {
                    mma16(c[mt][nt], al[mt], bh0, bh1);
                    mma16(c[mt][nt], ah[mt], bl0, bl1);
                    mma16(c[mt][nt], ah[mt], bh0, bh1);
                }
            }
        }
    }

    // epilogue: bias + store
    #pragma unroll
    for (int nt = 0; nt < 4; nt++) {
        int n = n0 + wn * 32 + nt * 8 + 2 * t;
        float b0 = bias[n], b1 = bias[n + 1];
        #pragma unroll
        for (int mt = 0; mt < 2; mt++) {
            int m = m0 + wm * 32 + mt * 16 + g;
            if (headmode) {
                int b_ = m >> 10, l = m & 1023;
                int h = n >> 6, dk = n & 63;
                float* p0 = C + (((size_t)b_ * HH + h) * LL + l) * DKK + dk;
                float* p1 = C + (((size_t)b_ * HH + h) * LL + (l + 8)) * DKK + dk;
                *(float2*)p0 = make_float2(c[mt][nt][0] + b0, c[mt][nt][1] + b1);
                *(float2*)p1 = make_float2(c[mt][nt][2] + b0, c[mt][nt][3] + b1);
            } else {
                float* p0 = C + (size_t)m * DD + n;
                float* p1 = C + (size_t)(m + 8) * DD + n;
                *(float2*)p0 = make_float2(c[mt][nt][0] + b0, c[mt][nt][1] + b1);
                *(float2*)p1 = make_float2(c[mt][nt][2] + b0, c[mt][nt][3] + b1);
            }
        }
    }
}

// ---------------------------------------------------------------------------
// Flash attention, 3xBF16 m16n8k16.
// Block = (bh, 64 q-rows), 128 threads (4 warps x 16 q-rows).
// QK^T and P@V both hi/lo split (3 MMAs per k16).
// smem (words): Kh/Kl [64][36], Vh/Vl [32][72], Ph/Pl [64][36] = 55,296 B.
// Strides: 36 -> bank (4g+... ) distinct; 72 -> bank (8t+g) distinct.
// ---------------------------------------------------------------------------
#define KP 36
#define VP 72
#define QSP 68
#define SMEM_ATTN ((2*64*KP + 2*32*VP + 2*64*KP) * (int)sizeof(unsigned))

__global__ __launch_bounds__(128, 3) void attn_bf16(
    const float* __restrict__ dist, const unsigned char* __restrict__ mask,
    const float* __restrict__ logwb)
{
    extern __shared__ unsigned smu[];
    unsigned* Kh = smu;                 // [64][KP]
    unsigned* Kl = Kh + 64*KP;
    unsigned* Vh = Kl + 64*KP;          // [32][VP]
    unsigned* Vl = Vh + 32*VP;
    unsigned* Ph = Vl + 32*VP;          // [64][KP]
    unsigned* Pl = Ph + 64*KP;
    float* Qstage = (float*)Ph;         // overlays Ph+Pl: 64*QSP=4352 <= 4608 words

    const int tid  = threadIdx.x;
    const int lane = tid & 31;
    const int warp = tid >> 5;
    const int g = lane >> 2, t = lane & 3;

    const int bh = blockIdx.y;
    const int b  = bh >> 3, h = bh & 7;
    const int q0 = blockIdx.x << 6;

    const float wb = __expf(logwb[h]);

    // Stage Q (scaled 0.125) into Qstage, then split into register frags.
    const float* Qg = g_Q + ((size_t)bh * LL + q0) * DKK;
    for (int i = tid; i < 1024; i += 128) {       // 64 rows x 16 float4
        int r = i >> 4, c4 = (i & 15) << 2;
        float4 v = *(const float4*)(Qg + (size_t)r * DKK + c4);
        v.x *= 0.125f; v.y *= 0.125f; v.z *= 0.125f; v.w *= 0.125f;
        *(float4*)&Qstage[r * QSP + c4] = v;
    }
    __syncthreads();

    unsigned qh[4][4], ql[4][4];
    {
        int r = warp * 16 + g;
        #pragma unroll
        for (int kt = 0; kt < 4; kt++) {
            int cb = kt*16 + 2*t;
            float2 f;
            f = *(const float2*)&Qstage[ r      * QSP + cb    ]; splitbf2(f.x, f.y, qh[kt][0], ql[kt][0]);
            f = *(const float2*)&Qstage[(r + 8) * QSP + cb    ]; splitbf2(f.x, f.y, qh[kt][1], ql[kt][1]);
            f = *(const float2*)&Qstage[ r      * QSP + cb + 8]; splitbf2(f.x, f.y, qh[kt][2], ql[kt][2]);
            f = *(const float2*)&Qstage[(r + 8) * QSP + cb + 8]; splitbf2(f.x, f.y, qh[kt][3], ql[kt][3]);
        }
    }

    float o[8][4];
    #pragma unroll
    for (int nt = 0; nt < 8; nt++)
        #pragma unroll
        for (int k = 0; k < 4; k++) o[nt][k] = 0.f;
    float mrow[2] = {-1e30f, -1e30f};
    float lrow[2] = {0.f, 0.f};

    const float* Kg = g_K + (size_t)bh * LL * DKK;
    const float* Vg = g_V + (size_t)bh * LL * DKK;
    const float* db = dist + (size_t)b * LL * LL;
    const unsigned char* mb = mask + (size_t)b * LL * LL;

    const int qr0 = q0 + warp * 16 + g;
    const int pr0 = warp * 16 + g;

    for (int k0 = 0; k0 < LL; k0 += 64) {
        __syncthreads();   // all warps done with previous K/V/P (and Qstage on iter 0)
        // K tile: [64 n][32 kpair] hi/lo
        for (int i = tid; i < 1024; i += 128) {
            int r = i >> 4, c4 = (i & 15) << 2;
            float4 kv = *(const float4*)(Kg + (size_t)(k0 + r) * DKK + c4);
            unsigned h0, l0, h1, l1;
            splitbf2(kv.x, kv.y, h0, l0);
            splitbf2(kv.z, kv.w, h1, l1);
            *(uint2*)&Kh[r*KP + (c4 >> 1)] = make_uint2(h0, h1);
            *(uint2*)&Kl[r*KP + (c4 >> 1)] = make_uint2(l0, l1);
        }
        // V tile: [32 kpair][64 n] hi/lo (pairs along k = rows)
        for (int i = tid; i < 512; i += 128) {
            int kp = i >> 4, c4 = (i & 15) << 2;
            float4 v0 = *(const float4*)(Vg + (size_t)(k0 + 2*kp    ) * DKK + c4);
            float4 v1 = *(const float4*)(Vg + (size_t)(k0 + 2*kp + 1) * DKK + c4);
            unsigned h0,l0,h1,l1,h2,l2,h3,l3;
            splitbf2(v0.x, v1.x, h0, l0);
            splitbf2(v0.y, v1.y, h1, l1);
            splitbf2(v0.z, v1.z, h2, l2);
            splitbf2(v0.w, v1.w, h3, l3);
            *(uint4*)&Vh[kp*VP + c4] = make_uint4(h0, h1, h2, h3);
            *(uint4*)&Vl[kp*VP + c4] = make_uint4(l0, l1, l2, l3);
        }
        __syncthreads();

        // S = Q @ K^T (3xBF16)
        float s[8][4];
        #pragma unroll
        for (int nt = 0; nt < 8; nt++)
            #pragma unroll
            for (int k = 0; k < 4; k++) s[nt][k] = 0.f;

        #pragma unroll
        for (int kt = 0; kt < 4; kt++) {
            #pragma unroll
            for (int nt = 0; nt < 8; nt++) {
                int br = (nt*8 + g) * KP + kt*8;
                unsigned bh0 = Kh[br + t], bh1 = Kh[br + t + 4];
                unsigned bl0 = Kl[br + t], bl1 = Kl[br + t + 4];
                mma16(s[nt], ql[kt], bh0, bh1);
                mma16(s[nt], qh[kt], bl0, bl1);
                mma16(s[nt], qh[kt], bh0, bh1);
            }
        }

        // distance bias + mask on C-fragments
        #pragma unroll
        for (int nt = 0; nt < 8; nt++) {
            int col = k0 + nt*8 + 2*t;
            float2 d0 = *(const float2*)(db + (size_t)qr0 * LL + col);
            float2 d1 = *(const float2*)(db + (size_t)(qr0 + 8) * LL + col);
            unsigned short mk0 = *(const unsigned short*)(mb + (size_t)qr0 * LL + col);
            unsigned short mk1 = *(const unsigned short*)(mb + (size_t)(qr0 + 8) * LL + col);
            s[nt][0] -= d0.x * wb; if (mk0 & 0xffu) s[nt][0] = -1e9f;
            s[nt][1] -= d0.y * wb; if (mk0 >> 8)    s[nt][1] = -1e9f;
            s[nt][2] -= d1.x * wb; if (mk1 & 0xffu) s[nt][2] = -1e9f;
            s[nt][3] -= d1.y * wb; if (mk1 >> 8)    s[nt][3] = -1e9f;
        }

        // online softmax
        #pragma unroll
        for (int i = 0; i < 2; i++) {
            float mx = -1e30f;
            #pragma unroll
            for (int nt = 0; nt < 8; nt++)
                mx = fmaxf(mx, fmaxf(s[nt][2*i], s[nt][2*i + 1]));
            mx = fmaxf(mx, __shfl_xor_sync(0xffffffffu, mx, 1));
            mx = fmaxf(mx, __shfl_xor_sync(0xffffffffu, mx, 2));
            float mnew  = fmaxf(mrow[i], mx);
            float alpha = __expf(mrow[i] - mnew);
            float sum = 0.f;
            #pragma unroll
            for (int nt = 0; nt < 8; nt++) {
                s[nt][2*i]     = __expf(s[nt][2*i]     - mnew);
                s[nt][2*i + 1] = __expf(s[nt][2*i + 1] - mnew);
                sum += s[nt][2*i] + s[nt][2*i + 1];
            }
            sum += __shfl_xor_sync(0xffffffffu, sum, 1);
            sum += __shfl_xor_sync(0xffffffffu, sum, 2);
            lrow[i] = lrow[i] * alpha + sum;
            mrow[i] = mnew;
            #pragma unroll
            for (int nt = 0; nt < 8; nt++) {
                o[nt][2*i]     *= alpha;
                o[nt][2*i + 1] *= alpha;
            }
        }

        // P hi/lo -> smem (warp-private rows). C-frag (c0,c1) is a k-pair.
        #pragma unroll
        for (int nt = 0; nt < 8; nt++) {
            int kp = nt*4 + t;
            unsigned h0, l0;
            splitbf2(s[nt][0], s[nt][1], h0, l0);
            Ph[ pr0      * KP + kp] = h0;
            Pl[ pr0      * KP + kp] = l0;
            splitbf2(s[nt][2], s[nt][3], h0, l0);
            Ph[(pr0 + 8) * KP + kp] = h0;
            Pl[(pr0 + 8) * KP + kp] = l0;
        }
        __syncwarp();

        // O += P @ V (3xBF16)
        #pragma unroll
        for (int kt = 0; kt < 4; kt++) {
            unsigned pah[4], pal[4];
            pah[0] = Ph[ pr0      * KP + kt*8 + t    ];
            pah[1] = Ph[(pr0 + 8) * KP + kt*8 + t    ];
            pah[2] = Ph[ pr0      * KP + kt*8 + t + 4];
            pah[3] = Ph[(pr0 + 8) * KP + kt*8 + t + 4];
            pal[0] = Pl[ pr0      * KP + kt*8 + t    ];
            pal[1] = Pl[(pr0 + 8) * KP + kt*8 + t    ];
            pal[2] = Pl[ pr0      * KP + kt*8 + t + 4];
            pal[3] = Pl[(pr0 + 8) * KP + kt*8 + t + 4];
            #pragma unroll
            for (int nt = 0; nt < 8; nt++) {
                unsigned vh0 = Vh[(kt*8 + t    ) * VP + nt*8 + g];
                unsigned vh1 = Vh[(kt*8 + t + 4) * VP + nt*8 + g];
                unsigned vl0 = Vl[(kt*8 + t    ) * VP + nt*8 + g];
                unsigned vl1 = Vl[(kt*8 + t + 4) * VP + nt*8 + g];
                mma16(o[nt], pah, vl0, vl1);
                mma16(o[nt], pal, vh0, vh1);
                mma16(o[nt], pah, vh0, vh1);
            }
        }
    }

    // normalize + write X (B,L,D)
    float inv0 = 1.0f / lrow[0], inv1 = 1.0f / lrow[1];
    float* X0 = g_X + ((size_t)b * LL + qr0)     * DD + h * DKK;
    float* X1 = g_X + ((size_t)b * LL + qr0 + 8) * DD + h * DKK;
    #pragma unroll
    for (int nt = 0; nt < 8; nt++) {
        *(float2*)&X0[nt*8 + 2*t] = make_float2(o[nt][0] * inv0, o[nt][1] * inv0);
        *(float2*)&X1[nt*8 + 2*t] = make_float2(o[nt][2] * inv1, o[nt][3] * inv1);
    }
}

// ---------------------------------------------------------------------------
extern "C" void kernel_launch(void* const* d_in, const int* in_sizes, int n_in,
                              void* d_out, int out_size)
{
    const float* query = (const float*)d_in[0];
    const float* key   = (const float*)d_in[1];
    const float* value = (const float*)d_in[2];
    const float* dist  = (const float*)d_in[3];
    const unsigned char* mask = (const unsigned char*)d_in[4];
    const float* Wq = (const float*)d_in[5];
    const float* bq = (const float*)d_in[6];
    const float* Wk = (const float*)d_in[7];
    const float* bk = (const float*)d_in[8];
    const float* Wv = (const float*)d_in[9];
    const float* bv = (const float*)d_in[10];
    const float* Wo = (const float*)d_in[11];
    const float* bo = (const float*)d_in[12];
    const float* logwb = (const float*)d_in[13];

    void *pQ, *pK, *pV, *pX;
    cudaGetSymbolAddress(&pQ, g_Q);
    cudaGetSymbolAddress(&pK, g_K);
    cudaGetSymbolAddress(&pV, g_V);
    cudaGetSymbolAddress(&pX, g_X);

    cudaFuncSetAttribute(attn_bf16,
                         cudaFuncAttributeMaxDynamicSharedMemorySize, SMEM_ATTN);

    dim3 gg(DD / 64, (BB * LL) / 128);   // (8, 64)
    gemm_bf16<<<gg, 256>>>(query, Wq, bq, (float*)pQ, 1);
    gemm_bf16<<<gg, 256>>>(key,   Wk, bk, (float*)pK, 1);
    gemm_bf16<<<gg, 256>>>(value, Wv, bv, (float*)pV, 1);

    attn_bf16<<<dim3(LL / 64, BB * HH), 128, SMEM_ATTN>>>(dist, mask, logwb);

    gemm_bf16<<<gg, 256>>>((const float*)pX, Wo, bo, (float*)d_out, 0);
}